// round 5
// baseline (speedup 1.0000x reference)
#include <cuda_runtime.h>
#include <cstdint>
#include <math.h>

#define TT    128
#define NSEQ  256
#define EMBED 512
#define UNITS 512
#define G4    2048

// ---------------- scratch (static device memory; no allocations) ----------------
__device__ __align__(256) float g_xW[2][TT][NSEQ][G4];   // 512 MB: xW+b, [dir][t][n][gatecol]
__device__ __align__(256) float g_Wt[2][EMBED][G4];      // tf32-rounded W (fwd,bwd)
__device__ __align__(256) float g_Ut[2][UNITS][G4];      // tf32-rounded U
__device__ __align__(256) float g_h[2][2][NSEQ][UNITS];  // [parity][dir][n][u]
__device__ __align__(256) float g_c[2][NSEQ][UNITS];     // [dir][n][u]

// ---------------- helpers ----------------
__device__ __forceinline__ uint32_t f2tf(float f) {
    uint32_t u; asm("cvt.rna.tf32.f32 %0, %1;" : "=r"(u) : "f"(f)); return u;
}
__device__ __forceinline__ void mma8(float* d, const uint32_t* a, const uint32_t* b) {
    asm volatile("mma.sync.aligned.m16n8k8.row.col.f32.tf32.tf32.f32 "
        "{%0,%1,%2,%3},{%4,%5,%6,%7},{%8,%9},{%0,%1,%2,%3};\n"
        : "+f"(d[0]), "+f"(d[1]), "+f"(d[2]), "+f"(d[3])
        : "r"(a[0]), "r"(a[1]), "r"(a[2]), "r"(a[3]), "r"(b[0]), "r"(b[1]));
}
__device__ __forceinline__ void cpa16(float* sm, const float* g) {
    uint32_t s = (uint32_t)__cvta_generic_to_shared(sm);
    asm volatile("cp.async.ca.shared.global [%0], [%1], 16;" :: "r"(s), "l"(g));
}
__device__ __forceinline__ void cpcommit() { asm volatile("cp.async.commit_group;"); }
template <int N> __device__ __forceinline__ void cpwait() {
    asm volatile("cp.async.wait_group %0;" :: "n"(N));
}
__device__ __forceinline__ float sigmoidf_(float z) {
    return 1.0f / (1.0f + __expf(-z));
}

// ---------------- prep: tf32-round W/U, zero h/c ----------------
__global__ void te_conv_kernel(const float* Wf, const float* Wb,
                               const float* Uf, const float* Ub) {
    int idx = blockIdx.x * 256 + threadIdx.x;          // 4 * 2^20 elements
    int which = idx >> 20, off = idx & 1048575;
    const float* src = (which == 0) ? Wf : (which == 1) ? Wb : (which == 2) ? Uf : Ub;
    float* dst = (which == 0) ? &g_Wt[0][0][0] : (which == 1) ? &g_Wt[1][0][0]
               : (which == 2) ? &g_Ut[0][0][0] : &g_Ut[1][0][0];
    dst[off] = __uint_as_float(f2tf(src[off]));
}

__global__ void te_zero_kernel() {
    int idx = blockIdx.x * 256 + threadIdx.x;          // 524288
    if (idx < 262144) (&g_h[0][0][0][0])[idx] = 0.0f;  // parity-0 h buffer
    else              (&g_c[0][0][0])[idx - 262144] = 0.0f;
}

// ---------------- projection: xW[dir][t] = emb[ids] @ W_dir + b_dir ----------------
// CTA tile 128x128, K-chunk 16, 256 threads (8 warps, warp tile 32x64).
#define P_AS 20     // As row stride (floats): 16 + 4 pad (conflict-free frag loads)
#define P_BS 136    // Bs row stride: 128 + 8 pad
__global__ __launch_bounds__(256) void te_proj_kernel(
        const int* __restrict__ x, const float* __restrict__ emb,
        const float* __restrict__ b_f, const float* __restrict__ b_b) {
    __shared__ __align__(16) float As[2][128 * P_AS];
    __shared__ __align__(16) float Bs[2][16 * P_BS];
    __shared__ int sid[128];

    int cta = blockIdx.x;                      // 2*128*2*16 = 8192
    int ct  = cta & 15;                        // col tile (128 cols)
    int mt  = (cta >> 4) & 1;                  // row tile (128 rows)
    int t   = (cta >> 5) & 127;
    int dir = cta >> 12;
    int n0 = mt * 128, c0 = ct * 128;
    int t_eff = dir ? (TT - 1 - t) : t;
    int tid = threadIdx.x;

    if (tid < 128) sid[tid] = x[(n0 + tid) * TT + t_eff];
    __syncthreads();

    const float* Wt = &g_Wt[dir][0][0];

    auto issue = [&](int kc, int bb) {
        int k0 = kc * 16;
        // A: 128 rows x 16 floats = 512 x 16B ops (2/thread)
        #pragma unroll
        for (int i = 0; i < 2; i++) {
            int o = tid + i * 256;
            int r = o >> 2, q = o & 3;
            cpa16(&As[bb][r * P_AS + q * 4],
                  emb + (size_t)sid[r] * EMBED + k0 + q * 4);
        }
        // B: 16 x 128 floats = 512 ops (2/thread)
        #pragma unroll
        for (int i = 0; i < 2; i++) {
            int o = tid + i * 256;
            int kk = o >> 5, q = o & 31;
            cpa16(&Bs[bb][kk * P_BS + q * 4],
                  Wt + (size_t)(k0 + kk) * G4 + c0 + q * 4);
        }
        cpcommit();
    };

    int lane = tid & 31, gid = lane >> 2, tig = lane & 3;
    int wid = tid >> 5, wy = wid >> 1, wx = wid & 1;
    int mbase = wy * 32, nbase = wx * 64;
    float acc[2][8][4];
    #pragma unroll
    for (int mi = 0; mi < 2; mi++)
        #pragma unroll
        for (int ni = 0; ni < 8; ni++)
            #pragma unroll
            for (int q = 0; q < 4; q++) acc[mi][ni][q] = 0.0f;

    auto compute = [&](int bb) {
        #pragma unroll
        for (int ks = 0; ks < 2; ks++) {
            int k = ks * 8;
            uint32_t a[2][4], b[8][2];
            #pragma unroll
            for (int mi = 0; mi < 2; mi++) {
                int m = mbase + mi * 16;
                a[mi][0] = f2tf(As[bb][(m + gid) * P_AS + k + tig]);
                a[mi][1] = f2tf(As[bb][(m + 8 + gid) * P_AS + k + tig]);
                a[mi][2] = f2tf(As[bb][(m + gid) * P_AS + k + tig + 4]);
                a[mi][3] = f2tf(As[bb][(m + 8 + gid) * P_AS + k + tig + 4]);
            }
            #pragma unroll
            for (int ni = 0; ni < 8; ni++) {
                int c = nbase + ni * 8 + gid;
                b[ni][0] = __float_as_uint(Bs[bb][(k + tig) * P_BS + c]);
                b[ni][1] = __float_as_uint(Bs[bb][(k + tig + 4) * P_BS + c]);
            }
            #pragma unroll
            for (int mi = 0; mi < 2; mi++)
                #pragma unroll
                for (int ni = 0; ni < 8; ni++)
                    mma8(acc[mi][ni], a[mi], b[ni]);
        }
    };

    const int NK = EMBED / 16;   // 32
    issue(0, 0);
    for (int kc = 0; kc < NK; kc++) {
        int bb = kc & 1;
        if (kc + 1 < NK) { issue(kc + 1, bb ^ 1); cpwait<1>(); }
        else             { cpwait<0>(); }
        __syncthreads();
        compute(bb);
        __syncthreads();
    }

    // epilogue: add bias, store to g_xW[dir][t]
    const float* bias = dir ? b_b : b_f;
    float* outp = &g_xW[dir][t][n0][0];
    #pragma unroll
    for (int mi = 0; mi < 2; mi++) {
        int r0 = mbase + mi * 16 + gid;
        #pragma unroll
        for (int ni = 0; ni < 8; ni++) {
            int c = c0 + nbase + ni * 8 + tig * 2;
            float b0v = bias[c], b1v = bias[c + 1];
            outp[(size_t)r0 * G4 + c]           = acc[mi][ni][0] + b0v;
            outp[(size_t)r0 * G4 + c + 1]       = acc[mi][ni][1] + b1v;
            outp[(size_t)(r0 + 8) * G4 + c]     = acc[mi][ni][2] + b0v;
            outp[(size_t)(r0 + 8) * G4 + c + 1] = acc[mi][ni][3] + b1v;
        }
    }
}

// ---------------- recurrent step: z = xW[t] + h@U ; gates ; h/c update ----------------
// CTA tile 64 rows x 64 gate-cols (16 units x 4 gates), K-chunk 32, 128 threads.
// h double-buffered by step parity (read par, write par^1) -> no cross-CTA race.
#define S_AS 36
#define S_BS 72
__global__ __launch_bounds__(128) void te_step_kernel(const int* __restrict__ x, int t) {
    __shared__ __align__(16) float smraw[2 * 64 * S_AS + 2 * 32 * S_BS];  // 9216 floats
    float* As = smraw;                    // [2][64*S_AS]
    float* Bsm = smraw + 2 * 64 * S_AS;   // [2][32*S_BS]
    float* Zs = smraw;                    // reuse for epilogue: 64*65 = 4160 floats

    int cta = blockIdx.x;                 // 2*4*32 = 256
    int ut  = cta & 31;                   // unit tile (16 units)
    int mt2 = (cta >> 5) & 3;             // row tile (64 rows)
    int dir = cta >> 7;
    int u0 = ut * 16, n0 = mt2 * 64;
    int par = t & 1;
    int tid = threadIdx.x;

    const float* hbuf = &g_h[par][dir][0][0];
    const float* Ut = &g_Ut[dir][0][0];

    auto issue = [&](int kc, int bb) {
        int k0 = kc * 32;
        // A: 64 rows x 32 floats = 512 x 16B ops (4/thread)
        #pragma unroll
        for (int i = 0; i < 4; i++) {
            int o = tid + i * 128;
            int r = o >> 3, q = o & 7;
            cpa16(&As[bb * (64 * S_AS) + r * S_AS + q * 4],
                  hbuf + (size_t)(n0 + r) * UNITS + k0 + q * 4);
        }
        // B: 32 k-rows x 64 cols; tile col c = gate*16 + lu -> global gate*512 + u0 + lu
        #pragma unroll
        for (int i = 0; i < 4; i++) {
            int o = tid + i * 128;
            int kk = o >> 4, q = o & 15;
            int col = (q >> 2) * 512 + u0 + (q & 3) * 4;
            cpa16(&Bsm[bb * (32 * S_BS) + kk * S_BS + q * 4],
                  Ut + (size_t)(k0 + kk) * G4 + col);
        }
        cpcommit();
    };

    int lane = tid & 31, gid = lane >> 2, tig = lane & 3;
    int wid = tid >> 5, wy = wid >> 1, wx = wid & 1;
    int mbase = wy * 32, nbase = wx * 32;
    float acc[2][4][4];
    #pragma unroll
    for (int mi = 0; mi < 2; mi++)
        #pragma unroll
        for (int ni = 0; ni < 4; ni++)
            #pragma unroll
            for (int q = 0; q < 4; q++) acc[mi][ni][q] = 0.0f;

    auto compute = [&](int bb) {
        float* Ab = As + bb * (64 * S_AS);
        float* Bb = Bsm + bb * (32 * S_BS);
        #pragma unroll
        for (int ks = 0; ks < 4; ks++) {
            int k = ks * 8;
            uint32_t a[2][4], b[4][2];
            #pragma unroll
            for (int mi = 0; mi < 2; mi++) {
                int m = mbase + mi * 16;
                a[mi][0] = f2tf(Ab[(m + gid) * S_AS + k + tig]);
                a[mi][1] = f2tf(Ab[(m + 8 + gid) * S_AS + k + tig]);
                a[mi][2] = f2tf(Ab[(m + gid) * S_AS + k + tig + 4]);
                a[mi][3] = f2tf(Ab[(m + 8 + gid) * S_AS + k + tig + 4]);
            }
            #pragma unroll
            for (int ni = 0; ni < 4; ni++) {
                int c = nbase + ni * 8 + gid;
                b[ni][0] = __float_as_uint(Bb[(k + tig) * S_BS + c]);
                b[ni][1] = __float_as_uint(Bb[(k + tig + 4) * S_BS + c]);
            }
            #pragma unroll
            for (int mi = 0; mi < 2; mi++)
                #pragma unroll
                for (int ni = 0; ni < 4; ni++)
                    mma8(acc[mi][ni], a[mi], b[ni]);
        }
    };

    const int NK = UNITS / 32;   // 16
    issue(0, 0);
    for (int kc = 0; kc < NK; kc++) {
        int bb = kc & 1;
        if (kc + 1 < NK) { issue(kc + 1, bb ^ 1); cpwait<1>(); }
        else             { cpwait<0>(); }
        __syncthreads();
        compute(bb);
        __syncthreads();
    }

    // stash z tile in SMEM (stride 65), then per-(row,unit) LSTM update
    #pragma unroll
    for (int mi = 0; mi < 2; mi++) {
        int r0 = mbase + mi * 16 + gid;
        #pragma unroll
        for (int ni = 0; ni < 4; ni++) {
            int c = nbase + ni * 8 + tig * 2;
            Zs[r0 * 65 + c]           = acc[mi][ni][0];
            Zs[r0 * 65 + c + 1]       = acc[mi][ni][1];
            Zs[(r0 + 8) * 65 + c]     = acc[mi][ni][2];
            Zs[(r0 + 8) * 65 + c + 1] = acc[mi][ni][3];
        }
    }
    __syncthreads();

    const float* xWp = &g_xW[dir][t][0][0];
    int t_eff = dir ? (TT - 1 - t) : t;
    #pragma unroll
    for (int it = 0; it < 8; it++) {
        int item = tid + it * 128;       // 64 rows x 16 units
        int r = item >> 4, lu = item & 15;
        int n = n0 + r, u = u0 + lu;
        const float* xr = xWp + (size_t)n * G4;
        float zi = Zs[r * 65 + lu]      + xr[u];
        float zf = Zs[r * 65 + 16 + lu] + xr[512 + u];
        float zg = Zs[r * 65 + 32 + lu] + xr[1024 + u];
        float zo = Zs[r * 65 + 48 + lu] + xr[1536 + u];
        float ig = sigmoidf_(zi);
        float fg = sigmoidf_(zf);
        float gg = tanhf(zg);
        float og = sigmoidf_(zo);
        float co = g_c[dir][n][u];
        float cn = fg * co + ig * gg;
        float hn = og * tanhf(cn);
        bool msk = (x[n * TT + t_eff] != 0);
        float ho = g_h[par][dir][n][u];
        g_h[par ^ 1][dir][n][u] = msk ? hn : ho;
        g_c[dir][n][u]          = msk ? cn : co;
    }
}

// ---------------- final: out[n] = concat(h_fwd, h_bwd) ----------------
__global__ void te_final_kernel(float* __restrict__ out) {
    int idx = blockIdx.x * 256 + threadIdx.x;   // 256*1024
    int n = idx >> 10, j = idx & 1023;
    out[idx] = (j < 512) ? g_h[0][0][n][j] : g_h[0][1][n][j - 512];
}

// ---------------- launch ----------------
extern "C" void kernel_launch(void* const* d_in, const int* in_sizes, int n_in,
                              void* d_out, int out_size) {
    const int*   x    = (const int*)d_in[0];
    const float* emb  = (const float*)d_in[1];
    const float* W_f  = (const float*)d_in[2];
    const float* U_f  = (const float*)d_in[3];
    const float* b_f  = (const float*)d_in[4];
    const float* W_b  = (const float*)d_in[5];
    const float* U_b  = (const float*)d_in[6];
    const float* b_b  = (const float*)d_in[7];
    float* out = (float*)d_out;

    te_conv_kernel<<<16384, 256>>>(W_f, W_b, U_f, U_b);
    te_zero_kernel<<<2048, 256>>>();
    te_proj_kernel<<<8192, 256>>>(x, emb, b_f, b_b);
    for (int t = 0; t < TT; t++)
        te_step_kernel<<<256, 128>>>(x, t);
    te_final_kernel<<<1024, 256>>>(out);
}

// round 6
// speedup vs baseline: 1.2700x; 1.2700x over previous
#include <cuda_runtime.h>
#include <cstdint>
#include <math.h>

#define TT    128
#define NSEQ  256
#define EMBED 512
#define UNITS 512
#define G4    2048

// ---------------- scratch (static device memory; no allocations) ----------------
__device__ __align__(256) float g_xW[2][TT][NSEQ][G4];   // 512 MB: xW+b, [dir][t][n][gatecol]
__device__ __align__(256) float g_Wt[2][EMBED][G4];      // tf32-rounded W (fwd,bwd)
__device__ __align__(256) float g_Ut[2][UNITS][G4];      // tf32-rounded U
__device__ __align__(256) float g_h[2][2][NSEQ][UNITS];  // [parity][dir][n][u]
__device__ __align__(256) float g_c[2][NSEQ][UNITS];     // [dir][n][u]

// ---------------- helpers ----------------
__device__ __forceinline__ uint32_t f2tf(float f) {
    uint32_t u; asm("cvt.rna.tf32.f32 %0, %1;" : "=r"(u) : "f"(f)); return u;
}
__device__ __forceinline__ void mma8(float* d, const uint32_t* a, const uint32_t* b) {
    asm volatile("mma.sync.aligned.m16n8k8.row.col.f32.tf32.tf32.f32 "
        "{%0,%1,%2,%3},{%4,%5,%6,%7},{%8,%9},{%0,%1,%2,%3};\n"
        : "+f"(d[0]), "+f"(d[1]), "+f"(d[2]), "+f"(d[3])
        : "r"(a[0]), "r"(a[1]), "r"(a[2]), "r"(a[3]), "r"(b[0]), "r"(b[1]));
}
__device__ __forceinline__ void cpa16(float* smp, const float* g) {
    uint32_t s = (uint32_t)__cvta_generic_to_shared(smp);
    asm volatile("cp.async.ca.shared.global [%0], [%1], 16;" :: "r"(s), "l"(g));
}
__device__ __forceinline__ void cpa4(void* smp, const void* g) {
    uint32_t s = (uint32_t)__cvta_generic_to_shared(smp);
    asm volatile("cp.async.ca.shared.global [%0], [%1], 4;" :: "r"(s), "l"(g));
}
__device__ __forceinline__ void cpcommit() { asm volatile("cp.async.commit_group;"); }
template <int N> __device__ __forceinline__ void cpwait() {
    asm volatile("cp.async.wait_group %0;" :: "n"(N));
}
__device__ __forceinline__ void qbar(int wg) {
    asm volatile("bar.sync %0, 128;" :: "r"(wg + 1) : "memory");
}
__device__ __forceinline__ float sigmoidf_(float z) {
    return 1.0f / (1.0f + __expf(-z));
}

// ---------------- prep: tf32-round W/U, zero h/c ----------------
__global__ void te_conv_kernel(const float* Wf, const float* Wb,
                               const float* Uf, const float* Ub) {
    int idx = blockIdx.x * 256 + threadIdx.x;          // 4 * 2^20 elements
    int which = idx >> 20, off = idx & 1048575;
    const float* src = (which == 0) ? Wf : (which == 1) ? Wb : (which == 2) ? Uf : Ub;
    float* dst = (which == 0) ? &g_Wt[0][0][0] : (which == 1) ? &g_Wt[1][0][0]
               : (which == 2) ? &g_Ut[0][0][0] : &g_Ut[1][0][0];
    dst[off] = __uint_as_float(f2tf(src[off]));
}

__global__ void te_zero_kernel() {
    int idx = blockIdx.x * 256 + threadIdx.x;          // 524288
    if (idx < 262144) (&g_h[0][0][0][0])[idx] = 0.0f;  // parity-0 h buffer
    else              (&g_c[0][0][0])[idx - 262144] = 0.0f;
}

// ---------------- projection: xW[dir][t] = emb[ids] @ W_dir + b_dir ----------------
// (unchanged from passing Round-5 kernel)
#define P_AS 20
#define P_BS 136
__global__ __launch_bounds__(256) void te_proj_kernel(
        const int* __restrict__ x, const float* __restrict__ emb,
        const float* __restrict__ b_f, const float* __restrict__ b_b) {
    __shared__ __align__(16) float As[2][128 * P_AS];
    __shared__ __align__(16) float Bs[2][16 * P_BS];
    __shared__ int sid[128];

    int cta = blockIdx.x;                      // 8192
    int ct  = cta & 15;
    int mt  = (cta >> 4) & 1;
    int t   = (cta >> 5) & 127;
    int dir = cta >> 12;
    int n0 = mt * 128, c0 = ct * 128;
    int t_eff = dir ? (TT - 1 - t) : t;
    int tid = threadIdx.x;

    if (tid < 128) sid[tid] = x[(n0 + tid) * TT + t_eff];
    __syncthreads();

    const float* Wt = &g_Wt[dir][0][0];

    auto issue = [&](int kc, int bb) {
        int k0 = kc * 16;
        #pragma unroll
        for (int i = 0; i < 2; i++) {
            int o = tid + i * 256;
            int r = o >> 2, q = o & 3;
            cpa16(&As[bb][r * P_AS + q * 4],
                  emb + (size_t)sid[r] * EMBED + k0 + q * 4);
        }
        #pragma unroll
        for (int i = 0; i < 2; i++) {
            int o = tid + i * 256;
            int kk = o >> 5, q = o & 31;
            cpa16(&Bs[bb][kk * P_BS + q * 4],
                  Wt + (size_t)(k0 + kk) * G4 + c0 + q * 4);
        }
        cpcommit();
    };

    int lane = tid & 31, gid = lane >> 2, tig = lane & 3;
    int wid = tid >> 5, wy = wid >> 1, wx = wid & 1;
    int mbase = wy * 32, nbase = wx * 64;
    float acc[2][8][4];
    #pragma unroll
    for (int mi = 0; mi < 2; mi++)
        #pragma unroll
        for (int ni = 0; ni < 8; ni++)
            #pragma unroll
            for (int q = 0; q < 4; q++) acc[mi][ni][q] = 0.0f;

    auto compute = [&](int bb) {
        #pragma unroll
        for (int ks = 0; ks < 2; ks++) {
            int k = ks * 8;
            uint32_t a[2][4], b[8][2];
            #pragma unroll
            for (int mi = 0; mi < 2; mi++) {
                int m = mbase + mi * 16;
                a[mi][0] = f2tf(As[bb][(m + gid) * P_AS + k + tig]);
                a[mi][1] = f2tf(As[bb][(m + 8 + gid) * P_AS + k + tig]);
                a[mi][2] = f2tf(As[bb][(m + gid) * P_AS + k + tig + 4]);
                a[mi][3] = f2tf(As[bb][(m + 8 + gid) * P_AS + k + tig + 4]);
            }
            #pragma unroll
            for (int ni = 0; ni < 8; ni++) {
                int c = nbase + ni * 8 + gid;
                b[ni][0] = __float_as_uint(Bs[bb][(k + tig) * P_BS + c]);
                b[ni][1] = __float_as_uint(Bs[bb][(k + tig + 4) * P_BS + c]);
            }
            #pragma unroll
            for (int mi = 0; mi < 2; mi++)
                #pragma unroll
                for (int ni = 0; ni < 8; ni++)
                    mma8(acc[mi][ni], a[mi], b[ni]);
        }
    };

    const int NK = EMBED / 16;   // 32
    issue(0, 0);
    for (int kc = 0; kc < NK; kc++) {
        int bb = kc & 1;
        if (kc + 1 < NK) { issue(kc + 1, bb ^ 1); cpwait<1>(); }
        else             { cpwait<0>(); }
        __syncthreads();
        compute(bb);
        __syncthreads();
    }

    const float* bias = dir ? b_b : b_f;
    float* outp = &g_xW[dir][t][n0][0];
    #pragma unroll
    for (int mi = 0; mi < 2; mi++) {
        int r0 = mbase + mi * 16 + gid;
        #pragma unroll
        for (int ni = 0; ni < 8; ni++) {
            int c = c0 + nbase + ni * 8 + tig * 2;
            float b0v = bias[c], b1v = bias[c + 1];
            outp[(size_t)r0 * G4 + c]           = acc[mi][ni][0] + b0v;
            outp[(size_t)r0 * G4 + c + 1]       = acc[mi][ni][1] + b1v;
            outp[(size_t)(r0 + 8) * G4 + c]     = acc[mi][ni][2] + b0v;
            outp[(size_t)(r0 + 8) * G4 + c + 1] = acc[mi][ni][3] + b1v;
        }
    }
}

// ---------------- recurrent step (REWRITTEN) ----------------
// CTA tile 64 rows x 64 gate-cols, 256 threads = 2 quads of 128.
// Quad wg computes K-half [wg*256, wg*256+256) in 8 chunks of 32 (2-stage
// cp.async pipeline, quad-scoped named barriers). Partials combined via SMEM.
// Epilogue data (xW tile / c / h_old / mask ids) prefetched at kernel entry so
// its DRAM latency overlaps the GEMM.
#define SA   36      // A chunk row stride (32 + 4 pad)
#define SB   72      // B chunk row stride (64 + 8 pad)
#define SQ   9216    // per-quad pipeline region (floats): 2*(64*SA) + 2*(32*SB)
#define ZST  80      // Z / xWs row stride (16B-aligned, conflict-clean)
#define STEP_SMEM_FLOATS (2 * SQ + 64 * ZST + 1024 + 1024 + 64)
#define STEP_SMEM_BYTES  (STEP_SMEM_FLOATS * 4)

__global__ __launch_bounds__(256) void te_step_kernel(const int* __restrict__ x, int t) {
    extern __shared__ __align__(16) float sm[];
    int tid  = threadIdx.x;
    int wg   = tid >> 7;          // quad id 0/1
    int qtid = tid & 127;

    int cta = blockIdx.x;         // 256 = 2 dirs * 4 row-tiles * 32 unit-tiles
    int ut  = cta & 31;
    int mt2 = (cta >> 5) & 3;
    int dir = cta >> 7;
    int u0 = ut * 16, n0 = mt2 * 64;
    int par = t & 1;
    int t_eff = dir ? (TT - 1 - t) : t;

    float* quadbase = sm + wg * SQ;            // A stages @0, B stages @4608
    float* xWs = sm + 2 * SQ;                  // 64*ZST
    float* cs  = xWs + 64 * ZST;               // 1024
    float* hs  = cs + 1024;                    // 1024
    int*  ids_s = (int*)(hs + 1024);           // 64

    const float* hbuf = &g_h[par][dir][0][0];
    const float* Ut   = &g_Ut[dir][0][0];
    const float* xWp  = &g_xW[dir][t][0][0];

    // ---- prefetch group (group 0): xW tile, c, h_old, mask ids ----
    #pragma unroll
    for (int i = 0; i < 4; i++) {
        int o = tid + i * 256;                 // 1024 = 64 rows * 4 gates * 4 vec4
        int r = o >> 4, g = (o >> 2) & 3, v = o & 3;
        cpa16(&xWs[r * ZST + g * 16 + v * 4],
              xWp + (size_t)(n0 + r) * G4 + g * 512 + u0 + v * 4);
    }
    {
        int r = tid >> 2, v = tid & 3;         // 256 = 64 rows * 4 vec4
        cpa16(&cs[r * 16 + v * 4], &g_c[dir][n0 + r][u0 + v * 4]);
        cpa16(&hs[r * 16 + v * 4], &g_h[par][dir][n0 + r][u0 + v * 4]);
    }
    if (tid < 64) cpa4(&ids_s[tid], &x[(n0 + tid) * TT + t_eff]);
    cpcommit();

    // ---- per-quad K-half pipeline ----
    int kq0 = wg * 256;
    auto issue = [&](int kc, int s) {
        int k0 = kq0 + kc * 32;
        float* A = quadbase + s * 2304;
        float* B = quadbase + 4608 + s * 2304;
        #pragma unroll
        for (int i = 0; i < 4; i++) {          // A: 64 rows x 32 fl = 512 vec4
            int o = qtid + i * 128;
            int r = o >> 3, v = o & 7;
            cpa16(&A[r * SA + v * 4], hbuf + (size_t)(n0 + r) * UNITS + k0 + v * 4);
        }
        #pragma unroll
        for (int i = 0; i < 4; i++) {          // B: 32 k x 64 cols = 512 vec4
            int o = qtid + i * 128;
            int kk = o >> 4, q = o & 15;
            int col = (q >> 2) * 512 + u0 + (q & 3) * 4;
            cpa16(&B[kk * SB + q * 4], Ut + (size_t)(k0 + kk) * G4 + col);
        }
        cpcommit();
    };

    int lane = tid & 31, gid = lane >> 2, tig = lane & 3;
    int wq = (tid >> 5) & 3, wy = wq >> 1, wx = wq & 1;
    int mbase = wy * 32, nbase = wx * 32;
    float acc[2][4][4];
    #pragma unroll
    for (int mi = 0; mi < 2; mi++)
        #pragma unroll
        for (int ni = 0; ni < 4; ni++)
            #pragma unroll
            for (int q = 0; q < 4; q++) acc[mi][ni][q] = 0.0f;

    auto compute = [&](int s) {
        float* Ab = quadbase + s * 2304;
        float* Bb = quadbase + 4608 + s * 2304;
        #pragma unroll
        for (int ks = 0; ks < 4; ks++) {
            int k = ks * 8;
            uint32_t a[2][4], b[4][2];
            #pragma unroll
            for (int mi = 0; mi < 2; mi++) {
                int m = mbase + mi * 16;
                a[mi][0] = f2tf(Ab[(m + gid) * SA + k + tig]);
                a[mi][1] = f2tf(Ab[(m + 8 + gid) * SA + k + tig]);
                a[mi][2] = f2tf(Ab[(m + gid) * SA + k + tig + 4]);
                a[mi][3] = f2tf(Ab[(m + 8 + gid) * SA + k + tig + 4]);
            }
            #pragma unroll
            for (int ni = 0; ni < 4; ni++) {
                int c = nbase + ni * 8 + gid;
                b[ni][0] = __float_as_uint(Bb[(k + tig) * SB + c]);
                b[ni][1] = __float_as_uint(Bb[(k + tig + 4) * SB + c]);
            }
            #pragma unroll
            for (int mi = 0; mi < 2; mi++)
                #pragma unroll
                for (int ni = 0; ni < 4; ni++)
                    mma8(acc[mi][ni], a[mi], b[ni]);
        }
    };

    issue(0, 0);
    for (int kc = 0; kc < 8; kc++) {
        int s = kc & 1;
        if (kc + 1 < 8) { issue(kc + 1, s ^ 1); cpwait<1>(); }
        else            { cpwait<0>(); }
        qbar(wg);
        compute(s);
        qbar(wg);
    }

    // ---- partials to SMEM (Z[wg] aliases this quad's dead pipeline region) ----
    float* Zq = quadbase;
    #pragma unroll
    for (int mi = 0; mi < 2; mi++) {
        int r0 = mbase + mi * 16 + gid;
        #pragma unroll
        for (int ni = 0; ni < 4; ni++) {
            int c = nbase + ni * 8 + tig * 2;
            Zq[r0 * ZST + c]           = acc[mi][ni][0];
            Zq[r0 * ZST + c + 1]       = acc[mi][ni][1];
            Zq[(r0 + 8) * ZST + c]     = acc[mi][ni][2];
            Zq[(r0 + 8) * ZST + c + 1] = acc[mi][ni][3];
        }
    }
    __syncthreads();

    // ---- LSTM gate update (all inputs already in SMEM) ----
    float* Z0 = sm;
    float* Z1 = sm + SQ;
    #pragma unroll
    for (int i = 0; i < 4; i++) {
        int item = tid + i * 256;              // 1024 = 64 rows * 16 units
        int r = item >> 4, lu = item & 15;
        int n = n0 + r, u = u0 + lu;
        float zi = Z0[r * ZST + lu]       + Z1[r * ZST + lu]       + xWs[r * ZST + lu];
        float zf = Z0[r * ZST + 16 + lu]  + Z1[r * ZST + 16 + lu]  + xWs[r * ZST + 16 + lu];
        float zg = Z0[r * ZST + 32 + lu]  + Z1[r * ZST + 32 + lu]  + xWs[r * ZST + 32 + lu];
        float zo = Z0[r * ZST + 48 + lu]  + Z1[r * ZST + 48 + lu]  + xWs[r * ZST + 48 + lu];
        float ig = sigmoidf_(zi);
        float fg = sigmoidf_(zf);
        float gg = tanhf(zg);
        float og = sigmoidf_(zo);
        float co = cs[r * 16 + lu];
        float cn = fg * co + ig * gg;
        float hn = og * tanhf(cn);
        bool msk = (ids_s[r] != 0);
        float ho = hs[r * 16 + lu];
        g_h[par ^ 1][dir][n][u] = msk ? hn : ho;
        g_c[dir][n][u]          = msk ? cn : co;
    }
}

// ---------------- final: out[n] = concat(h_fwd, h_bwd) ----------------
__global__ void te_final_kernel(float* __restrict__ out) {
    int idx = blockIdx.x * 256 + threadIdx.x;   // 256*1024
    int n = idx >> 10, j = idx & 1023;
    out[idx] = (j < 512) ? g_h[0][0][n][j] : g_h[0][1][n][j - 512];
}

// ---------------- launch ----------------
extern "C" void kernel_launch(void* const* d_in, const int* in_sizes, int n_in,
                              void* d_out, int out_size) {
    const int*   x    = (const int*)d_in[0];
    const float* emb  = (const float*)d_in[1];
    const float* W_f  = (const float*)d_in[2];
    const float* U_f  = (const float*)d_in[3];
    const float* b_f  = (const float*)d_in[4];
    const float* W_b  = (const float*)d_in[5];
    const float* U_b  = (const float*)d_in[6];
    const float* b_b  = (const float*)d_in[7];
    float* out = (float*)d_out;

    cudaFuncSetAttribute(te_step_kernel,
                         cudaFuncAttributeMaxDynamicSharedMemorySize, STEP_SMEM_BYTES);

    te_conv_kernel<<<16384, 256>>>(W_f, W_b, U_f, U_b);
    te_zero_kernel<<<2048, 256>>>();
    te_proj_kernel<<<8192, 256>>>(x, emb, b_f, b_b);
    for (int t = 0; t < TT; t++)
        te_step_kernel<<<256, 256, STEP_SMEM_BYTES>>>(x, t);
    te_final_kernel<<<1024, 256>>>(out);
}

// round 8
// speedup vs baseline: 1.4665x; 1.1547x over previous
#include <cuda_runtime.h>
#include <cstdint>
#include <math.h>

#define TT    128
#define NSEQ  256
#define EMBED 512
#define UNITS 512
#define G4    2048

// ---------------- scratch (static device memory; no allocations) ----------------
__device__ __align__(256) float g_xW[2][TT][NSEQ][G4];   // 512 MB: xW+b, [dir][t][n][gatecol]
__device__ __align__(256) float g_Wt[2][EMBED][G4];      // tf32-rounded W (fwd,bwd)
__device__ __align__(256) float g_Ut[2][UNITS][G4];      // tf32-rounded U
__device__ __align__(256) float g_h[2][2][NSEQ][UNITS];  // [parity][dir][n][u]
__device__ __align__(256) float g_c[2][NSEQ][UNITS];     // [dir][n][u]

// ---------------- helpers ----------------
__device__ __forceinline__ uint32_t f2tf(float f) {
    uint32_t u; asm("cvt.rna.tf32.f32 %0, %1;" : "=r"(u) : "f"(f)); return u;
}
__device__ __forceinline__ void mma8(float* d, const uint32_t* a, const uint32_t* b) {
    asm volatile("mma.sync.aligned.m16n8k8.row.col.f32.tf32.tf32.f32 "
        "{%0,%1,%2,%3},{%4,%5,%6,%7},{%8,%9},{%0,%1,%2,%3};\n"
        : "+f"(d[0]), "+f"(d[1]), "+f"(d[2]), "+f"(d[3])
        : "r"(a[0]), "r"(a[1]), "r"(a[2]), "r"(a[3]), "r"(b[0]), "r"(b[1]));
}
__device__ __forceinline__ void cpa16(float* smp, const float* g) {
    uint32_t s = (uint32_t)__cvta_generic_to_shared(smp);
    asm volatile("cp.async.ca.shared.global [%0], [%1], 16;" :: "r"(s), "l"(g));
}
__device__ __forceinline__ void cpa4(void* smp, const void* g) {
    uint32_t s = (uint32_t)__cvta_generic_to_shared(smp);
    asm volatile("cp.async.ca.shared.global [%0], [%1], 4;" :: "r"(s), "l"(g));
}
__device__ __forceinline__ void cpcommit() { asm volatile("cp.async.commit_group;"); }
template <int N> __device__ __forceinline__ void cpwait() {
    asm volatile("cp.async.wait_group %0;" :: "n"(N));
}
__device__ __forceinline__ void qbar(int wg) {
    asm volatile("bar.sync %0, 128;" :: "r"(wg + 1) : "memory");
}
__device__ __forceinline__ float sigmoidf_(float z) {
    return 1.0f / (1.0f + __expf(-z));
}

// ---------------- prep: tf32-round W/U, zero h/c ----------------
__global__ void te_conv_kernel(const float* Wf, const float* Wb,
                               const float* Uf, const float* Ub) {
    int idx = blockIdx.x * 256 + threadIdx.x;          // 4 * 2^20 elements
    int which = idx >> 20, off = idx & 1048575;
    const float* src = (which == 0) ? Wf : (which == 1) ? Wb : (which == 2) ? Uf : Ub;
    float* dst = (which == 0) ? &g_Wt[0][0][0] : (which == 1) ? &g_Wt[1][0][0]
               : (which == 2) ? &g_Ut[0][0][0] : &g_Ut[1][0][0];
    dst[off] = __uint_as_float(f2tf(src[off]));
}

__global__ void te_zero_kernel() {
    int idx = blockIdx.x * 256 + threadIdx.x;          // 524288
    if (idx < 262144) (&g_h[0][0][0][0])[idx] = 0.0f;  // parity-0 h buffer
    else              (&g_c[0][0][0])[idx - 262144] = 0.0f;
}

// ---------------- projection: xW[dir][t] = emb[ids] @ W_dir + b_dir ----------------
// (unchanged — passing since Round 5)
#define P_AS 20
#define P_BS 136
__global__ __launch_bounds__(256) void te_proj_kernel(
        const int* __restrict__ x, const float* __restrict__ emb,
        const float* __restrict__ b_f, const float* __restrict__ b_b) {
    __shared__ __align__(16) float As[2][128 * P_AS];
    __shared__ __align__(16) float Bs[2][16 * P_BS];
    __shared__ int sid[128];

    int cta = blockIdx.x;                      // 8192
    int ct  = cta & 15;
    int mt  = (cta >> 4) & 1;
    int t   = (cta >> 5) & 127;
    int dir = cta >> 12;
    int n0 = mt * 128, c0 = ct * 128;
    int t_eff = dir ? (TT - 1 - t) : t;
    int tid = threadIdx.x;

    if (tid < 128) sid[tid] = x[(n0 + tid) * TT + t_eff];
    __syncthreads();

    const float* Wt = &g_Wt[dir][0][0];

    auto issue = [&](int kc, int bb) {
        int k0 = kc * 16;
        #pragma unroll
        for (int i = 0; i < 2; i++) {
            int o = tid + i * 256;
            int r = o >> 2, q = o & 3;
            cpa16(&As[bb][r * P_AS + q * 4],
                  emb + (size_t)sid[r] * EMBED + k0 + q * 4);
        }
        #pragma unroll
        for (int i = 0; i < 2; i++) {
            int o = tid + i * 256;
            int kk = o >> 5, q = o & 31;
            cpa16(&Bs[bb][kk * P_BS + q * 4],
                  Wt + (size_t)(k0 + kk) * G4 + c0 + q * 4);
        }
        cpcommit();
    };

    int lane = tid & 31, gid = lane >> 2, tig = lane & 3;
    int wid = tid >> 5, wy = wid >> 1, wx = wid & 1;
    int mbase = wy * 32, nbase = wx * 64;
    float acc[2][8][4];
    #pragma unroll
    for (int mi = 0; mi < 2; mi++)
        #pragma unroll
        for (int ni = 0; ni < 8; ni++)
            #pragma unroll
            for (int q = 0; q < 4; q++) acc[mi][ni][q] = 0.0f;

    auto compute = [&](int bb) {
        #pragma unroll
        for (int ks = 0; ks < 2; ks++) {
            int k = ks * 8;
            uint32_t a[2][4], b[8][2];
            #pragma unroll
            for (int mi = 0; mi < 2; mi++) {
                int m = mbase + mi * 16;
                a[mi][0] = f2tf(As[bb][(m + gid) * P_AS + k + tig]);
                a[mi][1] = f2tf(As[bb][(m + 8 + gid) * P_AS + k + tig]);
                a[mi][2] = f2tf(As[bb][(m + gid) * P_AS + k + tig + 4]);
                a[mi][3] = f2tf(As[bb][(m + 8 + gid) * P_AS + k + tig + 4]);
            }
            #pragma unroll
            for (int ni = 0; ni < 8; ni++) {
                int c = nbase + ni * 8 + gid;
                b[ni][0] = __float_as_uint(Bs[bb][(k + tig) * P_BS + c]);
                b[ni][1] = __float_as_uint(Bs[bb][(k + tig + 4) * P_BS + c]);
            }
            #pragma unroll
            for (int mi = 0; mi < 2; mi++)
                #pragma unroll
                for (int ni = 0; ni < 8; ni++)
                    mma8(acc[mi][ni], a[mi], b[ni]);
        }
    };

    const int NK = EMBED / 16;   // 32
    issue(0, 0);
    for (int kc = 0; kc < NK; kc++) {
        int bb = kc & 1;
        if (kc + 1 < NK) { issue(kc + 1, bb ^ 1); cpwait<1>(); }
        else             { cpwait<0>(); }
        __syncthreads();
        compute(bb);
        __syncthreads();
    }

    const float* bias = dir ? b_b : b_f;
    float* outp = &g_xW[dir][t][n0][0];
    #pragma unroll
    for (int mi = 0; mi < 2; mi++) {
        int r0 = mbase + mi * 16 + gid;
        #pragma unroll
        for (int ni = 0; ni < 8; ni++) {
            int c = c0 + nbase + ni * 8 + tig * 2;
            float b0v = bias[c], b1v = bias[c + 1];
            outp[(size_t)r0 * G4 + c]           = acc[mi][ni][0] + b0v;
            outp[(size_t)r0 * G4 + c + 1]       = acc[mi][ni][1] + b1v;
            outp[(size_t)(r0 + 8) * G4 + c]     = acc[mi][ni][2] + b0v;
            outp[(size_t)(r0 + 8) * G4 + c + 1] = acc[mi][ni][3] + b1v;
        }
    }
}

// ---------------- recurrent step (retiled 64x128, 3-stage pipeline) ----------------
// Grid 128 CTAs (2 dirs * 4 row-tiles(64) * 16 unit-tiles(32 units -> 128 gate-cols)),
// 256 threads = 2 quads of 128; quad wg handles K-half [wg*256, wg*256+256) in
// 8 chunks of 32 with a 3-stage cp.async pipeline and ONE quad barrier per chunk.
// Epilogue inputs (xW tile / c / h_old / ids) prefetched at entry.
#define SA    36      // A chunk row stride (32 + 4)
#define SB    136     // B chunk row stride (128 + 8)
#define STG   6656    // floats per stage: 64*SA + 32*SB
#define SQ    (3 * STG)         // per-quad pipeline region (19968 floats)
#define ZST   136     // Z / xWs row stride
#define STEP_SMEM_FLOATS (2 * SQ + 64 * ZST + 2048 + 2048 + 64)
#define STEP_SMEM_BYTES  (STEP_SMEM_FLOATS * 4)

__global__ __launch_bounds__(256) void te_step_kernel(const int* __restrict__ x, int t) {
    extern __shared__ __align__(16) float sm[];
    int tid  = threadIdx.x;
    int wg   = tid >> 7;          // quad id 0/1
    int qtid = tid & 127;

    int cta = blockIdx.x;         // 128
    int ut  = cta & 15;           // 32-unit tile
    int mt2 = (cta >> 4) & 3;     // 64-row tile
    int dir = cta >> 6;
    int u0 = ut * 32, n0 = mt2 * 64;
    int par = t & 1;
    int t_eff = dir ? (TT - 1 - t) : t;

    float* quadbase = sm + wg * SQ;            // 3 stages: [A 64*SA | B 32*SB] each
    float* xWs = sm + 2 * SQ;                  // 64*ZST
    float* cs  = xWs + 64 * ZST;               // 2048 (64 rows x 32 units)
    float* hs  = cs + 2048;                    // 2048
    int*  ids_s = (int*)(hs + 2048);           // 64

    const float* hbuf = &g_h[par][dir][0][0];
    const float* Ut   = &g_Ut[dir][0][0];
    const float* xWp  = &g_xW[dir][t][0][0];

    // ---- prefetch (group P): xW tile (64x128 gate-cols), c, h_old, ids ----
    #pragma unroll
    for (int i = 0; i < 8; i++) {
        int o = tid + i * 256;                 // 2048 vec4 = 64 rows * 32 vec4
        int r = o >> 5, q = o & 31;            // q*4 = tile col: gate=(q>>3), lu=(q&7)*4
        cpa16(&xWs[r * ZST + q * 4],
              xWp + (size_t)(n0 + r) * G4 + (q >> 3) * 512 + u0 + (q & 7) * 4);
    }
    #pragma unroll
    for (int i = 0; i < 2; i++) {
        int o = tid + i * 256;                 // 512 vec4 = 64 rows * 8 vec4
        int r = o >> 3, v = o & 7;
        cpa16(&cs[r * 32 + v * 4], &g_c[dir][n0 + r][u0 + v * 4]);
        cpa16(&hs[r * 32 + v * 4], &g_h[par][dir][n0 + r][u0 + v * 4]);
    }
    if (tid < 64) cpa4(&ids_s[tid], &x[(n0 + tid) * TT + t_eff]);
    cpcommit();

    // ---- per-quad K-half pipeline (8 chunks of K=32, 3 stages) ----
    int kq0 = wg * 256;
    auto issue = [&](int kc, int s) {
        int k0 = kq0 + kc * 32;
        float* A = quadbase + s * STG;
        float* B = quadbase + s * STG + 64 * SA;
        #pragma unroll
        for (int i = 0; i < 4; i++) {          // A: 64 rows x 32 fl = 512 vec4
            int o = qtid + i * 128;
            int r = o >> 3, v = o & 7;
            cpa16(&A[r * SA + v * 4], hbuf + (size_t)(n0 + r) * UNITS + k0 + v * 4);
        }
        #pragma unroll
        for (int i = 0; i < 8; i++) {          // B: 32 k x 128 cols = 1024 vec4
            int o = qtid + i * 128;
            int kk = o >> 5, q = o & 31;
            int col = (q >> 3) * 512 + u0 + (q & 7) * 4;
            cpa16(&B[kk * SB + q * 4], Ut + (size_t)(k0 + kk) * G4 + col);
        }
        cpcommit();
    };

    int lane = tid & 31, gid = lane >> 2, tig = lane & 3;
    int wq = (tid >> 5) & 3, wy = wq >> 1, wx = wq & 1;
    int mbase = wy * 32, nbase = wx * 64;
    float acc[2][8][4];
    #pragma unroll
    for (int mi = 0; mi < 2; mi++)
        #pragma unroll
        for (int ni = 0; ni < 8; ni++)
            #pragma unroll
            for (int q = 0; q < 4; q++) acc[mi][ni][q] = 0.0f;

    auto compute = [&](int s) {
        float* Ab = quadbase + s * STG;
        float* Bb = quadbase + s * STG + 64 * SA;
        #pragma unroll
        for (int ks = 0; ks < 4; ks++) {
            int k = ks * 8;
            uint32_t a[2][4], b[8][2];
            #pragma unroll
            for (int mi = 0; mi < 2; mi++) {
                int m = mbase + mi * 16;
                a[mi][0] = f2tf(Ab[(m + gid) * SA + k + tig]);
                a[mi][1] = f2tf(Ab[(m + 8 + gid) * SA + k + tig]);
                a[mi][2] = f2tf(Ab[(m + gid) * SA + k + tig + 4]);
                a[mi][3] = f2tf(Ab[(m + 8 + gid) * SA + k + tig + 4]);
            }
            #pragma unroll
            for (int ni = 0; ni < 8; ni++) {
                int c = nbase + ni * 8 + gid;
                b[ni][0] = __float_as_uint(Bb[(k + tig) * SB + c]);
                b[ni][1] = __float_as_uint(Bb[(k + tig + 4) * SB + c]);
            }
            #pragma unroll
            for (int mi = 0; mi < 2; mi++)
                #pragma unroll
                for (int ni = 0; ni < 8; ni++)
                    mma8(acc[mi][ni], a[mi], b[ni]);
        }
    };

    // pipeline: preload 2, then 1 barrier per chunk.
    // WAR safety: issue(i+2) writes stage (i+2)%3 == (i-1)%3, last read at
    // compute(i-1); the qbar at iter i orders all quad warps past compute(i-1).
    issue(0, 0);
    issue(1, 1);
    for (int kc = 0; kc < 8; kc++) {
        int s = kc % 3;
        cpwait<1>();
        qbar(wg);
        if (kc + 2 < 8) issue(kc + 2, (kc + 2) % 3);
        compute(s);
    }
    cpwait<0>();
    qbar(wg);   // all quad warps past compute(7) before Z overwrites pipeline SMEM

    // ---- partials to SMEM (Z[wg] aliases this quad's dead pipeline region) ----
    float* Zq = quadbase;                       // 64*ZST = 8704 fl <= SQ
    #pragma unroll
    for (int mi = 0; mi < 2; mi++) {
        int r0 = mbase + mi * 16 + gid;
        #pragma unroll
        for (int ni = 0; ni < 8; ni++) {
            int c = nbase + ni * 8 + tig * 2;
            Zq[r0 * ZST + c]           = acc[mi][ni][0];
            Zq[r0 * ZST + c + 1]       = acc[mi][ni][1];
            Zq[(r0 + 8) * ZST + c]     = acc[mi][ni][2];
            Zq[(r0 + 8) * ZST + c + 1] = acc[mi][ni][3];
        }
    }
    __syncthreads();

    // ---- LSTM gate update (all inputs in SMEM); cols: gate*32 + lu ----
    float* Z0 = sm;
    float* Z1 = sm + SQ;
    #pragma unroll
    for (int i = 0; i < 8; i++) {
        int item = tid + i * 256;              // 2048 = 64 rows * 32 units
        int r = item >> 5, lu = item & 31;
        int n = n0 + r, u = u0 + lu;
        float zi = Z0[r * ZST + lu]      + Z1[r * ZST + lu]      + xWs[r * ZST + lu];
        float zf = Z0[r * ZST + 32 + lu] + Z1[r * ZST + 32 + lu] + xWs[r * ZST + 32 + lu];
        float zg = Z0[r * ZST + 64 + lu] + Z1[r * ZST + 64 + lu] + xWs[r * ZST + 64 + lu];
        float zo = Z0[r * ZST + 96 + lu] + Z1[r * ZST + 96 + lu] + xWs[r * ZST + 96 + lu];
        float ig = sigmoidf_(zi);
        float fg = sigmoidf_(zf);
        float gg = tanhf(zg);
        float og = sigmoidf_(zo);
        float co = cs[r * 32 + lu];
        float cn = fg * co + ig * gg;
        float hn = og * tanhf(cn);
        bool msk = (ids_s[r] != 0);
        float ho = hs[r * 32 + lu];
        g_h[par ^ 1][dir][n][u] = msk ? hn : ho;
        g_c[dir][n][u]          = msk ? cn : co;
    }
}

// ---------------- final: out[n] = concat(h_fwd, h_bwd) ----------------
__global__ void te_final_kernel(float* __restrict__ out) {
    int idx = blockIdx.x * 256 + threadIdx.x;   // 256*1024
    int n = idx >> 10, j = idx & 1023;
    out[idx] = (j < 512) ? g_h[0][0][n][j] : g_h[0][1][n][j - 512];
}

// ---------------- launch ----------------
extern "C" void kernel_launch(void* const* d_in, const int* in_sizes, int n_in,
                              void* d_out, int out_size) {
    const int*   x    = (const int*)d_in[0];
    const float* emb  = (const float*)d_in[1];
    const float* W_f  = (const float*)d_in[2];
    const float* U_f  = (const float*)d_in[3];
    const float* b_f  = (const float*)d_in[4];
    const float* W_b  = (const float*)d_in[5];
    const float* U_b  = (const float*)d_in[6];
    const float* b_b  = (const float*)d_in[7];
    float* out = (float*)d_out;

    cudaFuncSetAttribute(te_step_kernel,
                         cudaFuncAttributeMaxDynamicSharedMemorySize, STEP_SMEM_BYTES);

    te_conv_kernel<<<16384, 256>>>(W_f, W_b, U_f, U_b);
    te_zero_kernel<<<2048, 256>>>();
    te_proj_kernel<<<8192, 256>>>(x, emb, b_f, b_b);
    for (int t = 0; t < TT; t++)
        te_step_kernel<<<128, 256, STEP_SMEM_BYTES>>>(x, t);
    te_final_kernel<<<1024, 256>>>(out);
}

// round 11
// speedup vs baseline: 1.4874x; 1.0143x over previous
#include <cuda_runtime.h>
#include <cstdint>
#include <math.h>

#define TT    128
#define NSEQ  256
#define EMBED 512
#define UNITS 512
#define G4    2048

// ---------------- scratch (static device memory; no allocations) ----------------
__device__ __align__(256) float g_xW[2][TT][NSEQ][G4];   // 512 MB: xW+b, [dir][t][n][gatecol]
__device__ __align__(256) float g_Wt[2][EMBED][G4];      // tf32-rounded W (fwd,bwd)
__device__ __align__(256) float g_Ut[2][UNITS][G4];      // tf32-rounded U
__device__ __align__(256) float g_h[2][2][NSEQ][UNITS];  // [parity][dir][n][u]
__device__ __align__(256) float g_c[2][NSEQ][UNITS];     // [dir][n][u]

// ---------------- helpers ----------------
__device__ __forceinline__ uint32_t f2tf(float f) {
    uint32_t u; asm("cvt.rna.tf32.f32 %0, %1;" : "=r"(u) : "f"(f)); return u;
}
__device__ __forceinline__ void mma8(float* d, const uint32_t* a, const uint32_t* b) {
    asm volatile("mma.sync.aligned.m16n8k8.row.col.f32.tf32.tf32.f32 "
        "{%0,%1,%2,%3},{%4,%5,%6,%7},{%8,%9},{%0,%1,%2,%3};\n"
        : "+f"(d[0]), "+f"(d[1]), "+f"(d[2]), "+f"(d[3])
        : "r"(a[0]), "r"(a[1]), "r"(a[2]), "r"(a[3]), "r"(b[0]), "r"(b[1]));
}
__device__ __forceinline__ void cpa16(float* smp, const float* g) {
    uint32_t s = (uint32_t)__cvta_generic_to_shared(smp);
    asm volatile("cp.async.ca.shared.global [%0], [%1], 16;" :: "r"(s), "l"(g));
}
__device__ __forceinline__ void cpa4(void* smp, const void* g) {
    uint32_t s = (uint32_t)__cvta_generic_to_shared(smp);
    asm volatile("cp.async.ca.shared.global [%0], [%1], 4;" :: "r"(s), "l"(g));
}
__device__ __forceinline__ void cpcommit() { asm volatile("cp.async.commit_group;"); }
template <int N> __device__ __forceinline__ void cpwait() {
    asm volatile("cp.async.wait_group %0;" :: "n"(N));
}
__device__ __forceinline__ void qbar(int wg) {
    asm volatile("bar.sync %0, 128;" :: "r"(wg + 1) : "memory");
}
__device__ __forceinline__ float sigmoidf_(float z) {
    return 1.0f / (1.0f + __expf(-z));
}

// ---------------- prep: tf32-round W/U, zero h/c ----------------
__global__ void te_conv_kernel(const float* Wf, const float* Wb,
                               const float* Uf, const float* Ub) {
    int idx = blockIdx.x * 256 + threadIdx.x;          // 4 * 2^20 elements
    int which = idx >> 20, off = idx & 1048575;
    const float* src = (which == 0) ? Wf : (which == 1) ? Wb : (which == 2) ? Uf : Ub;
    float* dst = (which == 0) ? &g_Wt[0][0][0] : (which == 1) ? &g_Wt[1][0][0]
               : (which == 2) ? &g_Ut[0][0][0] : &g_Ut[1][0][0];
    dst[off] = __uint_as_float(f2tf(src[off]));
}

__global__ void te_zero_kernel() {
    int idx = blockIdx.x * 256 + threadIdx.x;          // 524288
    if (idx < 262144) (&g_h[0][0][0][0])[idx] = 0.0f;  // parity-0 h buffer
    else              (&g_c[0][0][0])[idx - 262144] = 0.0f;
}

// ---------------- projection: xW[dir][t] = emb[ids] @ W_dir + b_dir ----------------
// (unchanged — passing since Round 5)
#define P_AS 20
#define P_BS 136
__global__ __launch_bounds__(256) void te_proj_kernel(
        const int* __restrict__ x, const float* __restrict__ emb,
        const float* __restrict__ b_f, const float* __restrict__ b_b) {
    __shared__ __align__(16) float As[2][128 * P_AS];
    __shared__ __align__(16) float Bs[2][16 * P_BS];
    __shared__ int sid[128];

    int cta = blockIdx.x;                      // 8192
    int ct  = cta & 15;
    int mt  = (cta >> 4) & 1;
    int t   = (cta >> 5) & 127;
    int dir = cta >> 12;
    int n0 = mt * 128, c0 = ct * 128;
    int t_eff = dir ? (TT - 1 - t) : t;
    int tid = threadIdx.x;

    if (tid < 128) sid[tid] = x[(n0 + tid) * TT + t_eff];
    __syncthreads();

    const float* Wt = &g_Wt[dir][0][0];

    auto issue = [&](int kc, int bb) {
        int k0 = kc * 16;
        #pragma unroll
        for (int i = 0; i < 2; i++) {
            int o = tid + i * 256;
            int r = o >> 2, q = o & 3;
            cpa16(&As[bb][r * P_AS + q * 4],
                  emb + (size_t)sid[r] * EMBED + k0 + q * 4);
        }
        #pragma unroll
        for (int i = 0; i < 2; i++) {
            int o = tid + i * 256;
            int kk = o >> 5, q = o & 31;
            cpa16(&Bs[bb][kk * P_BS + q * 4],
                  Wt + (size_t)(k0 + kk) * G4 + c0 + q * 4);
        }
        cpcommit();
    };

    int lane = tid & 31, gid = lane >> 2, tig = lane & 3;
    int wid = tid >> 5, wy = wid >> 1, wx = wid & 1;
    int mbase = wy * 32, nbase = wx * 64;
    float acc[2][8][4];
    #pragma unroll
    for (int mi = 0; mi < 2; mi++)
        #pragma unroll
        for (int ni = 0; ni < 8; ni++)
            #pragma unroll
            for (int q = 0; q < 4; q++) acc[mi][ni][q] = 0.0f;

    auto compute = [&](int bb) {
        #pragma unroll
        for (int ks = 0; ks < 2; ks++) {
            int k = ks * 8;
            uint32_t a[2][4], b[8][2];
            #pragma unroll
            for (int mi = 0; mi < 2; mi++) {
                int m = mbase + mi * 16;
                a[mi][0] = f2tf(As[bb][(m + gid) * P_AS + k + tig]);
                a[mi][1] = f2tf(As[bb][(m + 8 + gid) * P_AS + k + tig]);
                a[mi][2] = f2tf(As[bb][(m + gid) * P_AS + k + tig + 4]);
                a[mi][3] = f2tf(As[bb][(m + 8 + gid) * P_AS + k + tig + 4]);
            }
            #pragma unroll
            for (int ni = 0; ni < 8; ni++) {
                int c = nbase + ni * 8 + gid;
                b[ni][0] = __float_as_uint(Bs[bb][(k + tig) * P_BS + c]);
                b[ni][1] = __float_as_uint(Bs[bb][(k + tig + 4) * P_BS + c]);
            }
            #pragma unroll
            for (int mi = 0; mi < 2; mi++)
                #pragma unroll
                for (int ni = 0; ni < 8; ni++)
                    mma8(acc[mi][ni], a[mi], b[ni]);
        }
    };

    const int NK = EMBED / 16;   // 32
    issue(0, 0);
    for (int kc = 0; kc < NK; kc++) {
        int bb = kc & 1;
        if (kc + 1 < NK) { issue(kc + 1, bb ^ 1); cpwait<1>(); }
        else             { cpwait<0>(); }
        __syncthreads();
        compute(bb);
        __syncthreads();
    }

    const float* bias = dir ? b_b : b_f;
    float* outp = &g_xW[dir][t][n0][0];
    #pragma unroll
    for (int mi = 0; mi < 2; mi++) {
        int r0 = mbase + mi * 16 + gid;
        #pragma unroll
        for (int ni = 0; ni < 8; ni++) {
            int c = c0 + nbase + ni * 8 + tig * 2;
            float b0v = bias[c], b1v = bias[c + 1];
            outp[(size_t)r0 * G4 + c]           = acc[mi][ni][0] + b0v;
            outp[(size_t)r0 * G4 + c + 1]       = acc[mi][ni][1] + b1v;
            outp[(size_t)(r0 + 8) * G4 + c]     = acc[mi][ni][2] + b0v;
            outp[(size_t)(r0 + 8) * G4 + c + 1] = acc[mi][ni][3] + b1v;
        }
    }
}

// ---------------- recurrent step (64x128 tile, 512 threads = 4 K-quads) ----------------
// Grid 128 CTAs (2 dirs * 4 row-tiles(64) * 16 unit-tiles(32 units -> 128 gate-cols)).
// Quad wg (128 thr) owns K-quarter [wg*128, wg*128+128) in 8 chunks of K=16,
// 3-stage cp.async pipeline, 1 quad barrier per chunk. 16 warps/SM for latency hiding.
// Epilogue sums 4 partials; inputs (xW tile / c / h_old / ids) prefetched at entry.
#define SA4   20      // A chunk row stride (16 + 4)
#define SB4   136     // B chunk row stride (128 + 8)
#define STG4  3456    // floats per stage: 64*SA4 + 16*SB4
#define SQ4   (3 * STG4)        // per-quad pipeline region (10368 floats)
#define ZST   136     // Z / xWs row stride
#define STEP_SMEM_FLOATS (4 * SQ4 + 64 * ZST + 2048 + 2048 + 64)   // 54336
#define STEP_SMEM_BYTES  (STEP_SMEM_FLOATS * 4)                     // 217344

__global__ __launch_bounds__(512) void te_step_kernel(const int* __restrict__ x, int t) {
    extern __shared__ __align__(16) float sm[];
    int tid  = threadIdx.x;
    int wg   = tid >> 7;          // quad id 0..3
    int qtid = tid & 127;

    int cta = blockIdx.x;         // 128
    int ut  = cta & 15;           // 32-unit tile
    int mt2 = (cta >> 4) & 3;     // 64-row tile
    int dir = cta >> 6;
    int u0 = ut * 32, n0 = mt2 * 64;
    int par = t & 1;
    int t_eff = dir ? (TT - 1 - t) : t;

    float* quadbase = sm + wg * SQ4;           // 3 stages: [A 64*SA4 | B 16*SB4]
    float* xWs = sm + 4 * SQ4;                 // 64*ZST
    float* cs  = xWs + 64 * ZST;               // 2048 (64 rows x 32 units)
    float* hs  = cs + 2048;                    // 2048
    int*  ids_s = (int*)(hs + 2048);           // 64

    const float* hbuf = &g_h[par][dir][0][0];
    const float* Ut   = &g_Ut[dir][0][0];
    const float* xWp  = &g_xW[dir][t][0][0];

    // ---- prefetch (group P): xW tile (64x128 gate-cols), c, h_old, ids ----
    #pragma unroll
    for (int i = 0; i < 4; i++) {
        int o = tid + i * 512;                 // 2048 vec4 = 64 rows * 32 vec4
        int r = o >> 5, q = o & 31;            // tile col: gate=(q>>3), lu=(q&7)*4
        cpa16(&xWs[r * ZST + q * 4],
              xWp + (size_t)(n0 + r) * G4 + (q >> 3) * 512 + u0 + (q & 7) * 4);
    }
    {
        int r = tid >> 3, v = tid & 7;         // 512 vec4 = 64 rows * 8 vec4
        cpa16(&cs[r * 32 + v * 4], &g_c[dir][n0 + r][u0 + v * 4]);
        cpa16(&hs[r * 32 + v * 4], &g_h[par][dir][n0 + r][u0 + v * 4]);
    }
    if (tid < 64) cpa4(&ids_s[tid], &x[(n0 + tid) * TT + t_eff]);
    cpcommit();

    // ---- per-quad K-quarter pipeline (8 chunks of K=16, 3 stages) ----
    int kq0 = wg * 128;
    auto issue = [&](int kc, int s) {
        int k0 = kq0 + kc * 16;
        float* A = quadbase + s * STG4;
        float* B = quadbase + s * STG4 + 64 * SA4;
        #pragma unroll
        for (int i = 0; i < 2; i++) {          // A: 64 rows x 16 fl = 256 vec4
            int o = qtid + i * 128;
            int r = o >> 2, v = o & 3;
            cpa16(&A[r * SA4 + v * 4], hbuf + (size_t)(n0 + r) * UNITS + k0 + v * 4);
        }
        #pragma unroll
        for (int i = 0; i < 4; i++) {          // B: 16 k x 128 cols = 512 vec4
            int o = qtid + i * 128;
            int kk = o >> 5, q = o & 31;
            int col = (q >> 3) * 512 + u0 + (q & 7) * 4;
            cpa16(&B[kk * SB4 + q * 4], Ut + (size_t)(k0 + kk) * G4 + col);
        }
        cpcommit();
    };

    int lane = tid & 31, gid = lane >> 2, tig = lane & 3;
    int wq = (tid >> 5) & 3, wy = wq >> 1, wx = wq & 1;
    int mbase = wy * 32, nbase = wx * 64;
    float acc[2][8][4];
    #pragma unroll
    for (int mi = 0; mi < 2; mi++)
        #pragma unroll
        for (int ni = 0; ni < 8; ni++)
            #pragma unroll
            for (int q = 0; q < 4; q++) acc[mi][ni][q] = 0.0f;

    auto compute = [&](int s) {
        float* Ab = quadbase + s * STG4;
        float* Bb = quadbase + s * STG4 + 64 * SA4;
        #pragma unroll
        for (int ks = 0; ks < 2; ks++) {
            int k = ks * 8;
            uint32_t a[2][4], b[8][2];
            #pragma unroll
            for (int mi = 0; mi < 2; mi++) {
                int m = mbase + mi * 16;
                a[mi][0] = f2tf(Ab[(m + gid) * SA4 + k + tig]);
                a[mi][1] = f2tf(Ab[(m + 8 + gid) * SA4 + k + tig]);
                a[mi][2] = f2tf(Ab[(m + gid) * SA4 + k + tig + 4]);
                a[mi][3] = f2tf(Ab[(m + 8 + gid) * SA4 + k + tig + 4]);
            }
            #pragma unroll
            for (int ni = 0; ni < 8; ni++) {
                int c = nbase + ni * 8 + gid;
                b[ni][0] = __float_as_uint(Bb[(k + tig) * SB4 + c]);
                b[ni][1] = __float_as_uint(Bb[(k + tig + 4) * SB4 + c]);
            }
            #pragma unroll
            for (int mi = 0; mi < 2; mi++)
                #pragma unroll
                for (int ni = 0; ni < 8; ni++)
                    mma8(acc[mi][ni], a[mi], b[ni]);
        }
    };

    // pipeline: preload 2, then 1 quad barrier per chunk.
    // WAR: issue(i+2) writes stage (i+2)%3 == (i-1)%3, last read at compute(i-1);
    // the qbar at iter i orders all quad warps past compute(i-1).
    issue(0, 0);
    issue(1, 1);
    for (int kc = 0; kc < 8; kc++) {
        int s = kc % 3;
        cpwait<1>();
        qbar(wg);
        if (kc + 2 < 8) issue(kc + 2, (kc + 2) % 3);
        compute(s);
    }
    cpwait<0>();
    qbar(wg);   // all quad warps past compute(7) before Z overwrites pipeline SMEM

    // ---- partials to SMEM (Z[wg] aliases this quad's dead pipeline region) ----
    float* Zq = quadbase;                      // 64*ZST = 8704 fl <= SQ4
    #pragma unroll
    for (int mi = 0; mi < 2; mi++) {
        int r0 = mbase + mi * 16 + gid;
        #pragma unroll
        for (int ni = 0; ni < 8; ni++) {
            int c = nbase + ni * 8 + tig * 2;
            Zq[r0 * ZST + c]           = acc[mi][ni][0];
            Zq[r0 * ZST + c + 1]       = acc[mi][ni][1];
            Zq[(r0 + 8) * ZST + c]     = acc[mi][ni][2];
            Zq[(r0 + 8) * ZST + c + 1] = acc[mi][ni][3];
        }
    }
    __syncthreads();

    // ---- LSTM gate update (sum 4 partials + xW); cols: gate*32 + lu ----
    float* Z0 = sm;
    float* Z1 = sm + SQ4;
    float* Z2 = sm + 2 * SQ4;
    float* Z3 = sm + 3 * SQ4;
    #pragma unroll
    for (int i = 0; i < 4; i++) {
        int item = tid + i * 512;              // 2048 = 64 rows * 32 units
        int r = item >> 5, lu = item & 31;
        int n = n0 + r, u = u0 + lu;
        float zi = Z0[r * ZST + lu]      + Z1[r * ZST + lu]
                 + Z2[r * ZST + lu]      + Z3[r * ZST + lu]      + xWs[r * ZST + lu];
        float zf = Z0[r * ZST + 32 + lu] + Z1[r * ZST + 32 + lu]
                 + Z2[r * ZST + 32 + lu] + Z3[r * ZST + 32 + lu] + xWs[r * ZST + 32 + lu];
        float zg = Z0[r * ZST + 64 + lu] + Z1[r * ZST + 64 + lu]
                 + Z2[r * ZST + 64 + lu] + Z3[r * ZST + 64 + lu] + xWs[r * ZST + 64 + lu];
        float zo = Z0[r * ZST + 96 + lu] + Z1[r * ZST + 96 + lu]
                 + Z2[r * ZST + 96 + lu] + Z3[r * ZST + 96 + lu] + xWs[r * ZST + 96 + lu];
        float ig = sigmoidf_(zi);
        float fg = sigmoidf_(zf);
        float gg = tanhf(zg);
        float og = sigmoidf_(zo);
        float co = cs[r * 32 + lu];
        float cn = fg * co + ig * gg;
        float hn = og * tanhf(cn);
        bool msk = (ids_s[r] != 0);
        float ho = hs[r * 32 + lu];
        g_h[par ^ 1][dir][n][u] = msk ? hn : ho;
        g_c[dir][n][u]          = msk ? cn : co;
    }
}

// ---------------- final: out[n] = concat(h_fwd, h_bwd) ----------------
__global__ void te_final_kernel(float* __restrict__ out) {
    int idx = blockIdx.x * 256 + threadIdx.x;   // 256*1024
    int n = idx >> 10, j = idx & 1023;
    out[idx] = (j < 512) ? g_h[0][0][n][j] : g_h[0][1][n][j - 512];
}

// ---------------- launch ----------------
extern "C" void kernel_launch(void* const* d_in, const int* in_sizes, int n_in,
                              void* d_out, int out_size) {
    const int*   x    = (const int*)d_in[0];
    const float* emb  = (const float*)d_in[1];
    const float* W_f  = (const float*)d_in[2];
    const float* U_f  = (const float*)d_in[3];
    const float* b_f  = (const float*)d_in[4];
    const float* W_b  = (const float*)d_in[5];
    const float* U_b  = (const float*)d_in[6];
    const float* b_b  = (const float*)d_in[7];
    float* out = (float*)d_out;

    cudaFuncSetAttribute(te_step_kernel,
                         cudaFuncAttributeMaxDynamicSharedMemorySize, STEP_SMEM_BYTES);

    te_conv_kernel<<<16384, 256>>>(W_f, W_b, U_f, U_b);
    te_zero_kernel<<<2048, 256>>>();
    te_proj_kernel<<<8192, 256>>>(x, emb, b_f, b_b);
    for (int t = 0; t < TT; t++)
        te_step_kernel<<<128, 512, STEP_SMEM_BYTES>>>(x, t);
    te_final_kernel<<<1024, 256>>>(out);
}

// round 14
// speedup vs baseline: 1.4877x; 1.0001x over previous
#include <cuda_runtime.h>
#include <cstdint>
#include <math.h>

#define TT    128
#define NSEQ  256
#define EMBED 512
#define UNITS 512
#define G4    2048

// ---------------- scratch (static device memory; no allocations) ----------------
__device__ __align__(256) float g_xW[2][TT][NSEQ][G4];   // 512 MB: xW+b, [dir][t][n][gatecol]
__device__ __align__(256) float g_Wt[2][EMBED][G4];      // tf32-rounded W (fwd,bwd)
__device__ __align__(256) float g_Ut[2][UNITS][G4];      // tf32-rounded U
__device__ __align__(256) float g_h[2][2][NSEQ][UNITS];  // [parity][dir][n][u]
__device__ __align__(256) float g_c[2][NSEQ][UNITS];     // [dir][n][u]

// ---------------- helpers ----------------
__device__ __forceinline__ uint32_t f2tf(float f) {
    uint32_t u; asm("cvt.rna.tf32.f32 %0, %1;" : "=r"(u) : "f"(f)); return u;
}
__device__ __forceinline__ void mma8(float* d, const uint32_t* a, const uint32_t* b) {
    asm volatile("mma.sync.aligned.m16n8k8.row.col.f32.tf32.tf32.f32 "
        "{%0,%1,%2,%3},{%4,%5,%6,%7},{%8,%9},{%0,%1,%2,%3};\n"
        : "+f"(d[0]), "+f"(d[1]), "+f"(d[2]), "+f"(d[3])
        : "r"(a[0]), "r"(a[1]), "r"(a[2]), "r"(a[3]), "r"(b[0]), "r"(b[1]));
}
__device__ __forceinline__ void cpa16(float* smp, const float* g) {
    uint32_t s = (uint32_t)__cvta_generic_to_shared(smp);
    asm volatile("cp.async.ca.shared.global [%0], [%1], 16;" :: "r"(s), "l"(g));
}
// cp.async with an L2 cache policy (createpolicy-based hint)
__device__ __forceinline__ void cpa16p(float* smp, const float* g, uint64_t pol) {
    uint32_t s = (uint32_t)__cvta_generic_to_shared(smp);
    asm volatile("cp.async.ca.shared.global.L2::cache_hint [%0], [%1], 16, %2;"
                 :: "r"(s), "l"(g), "l"(pol));
}
__device__ __forceinline__ uint64_t mkpol_evict_last() {
    uint64_t p; asm("createpolicy.fractional.L2::evict_last.b64 %0, 1.0;" : "=l"(p));
    return p;
}
__device__ __forceinline__ uint64_t mkpol_evict_first() {
    uint64_t p; asm("createpolicy.fractional.L2::evict_first.b64 %0, 1.0;" : "=l"(p));
    return p;
}
__device__ __forceinline__ void cpa4(void* smp, const void* g) {
    uint32_t s = (uint32_t)__cvta_generic_to_shared(smp);
    asm volatile("cp.async.ca.shared.global [%0], [%1], 4;" :: "r"(s), "l"(g));
}
__device__ __forceinline__ void cpcommit() { asm volatile("cp.async.commit_group;"); }
template <int N> __device__ __forceinline__ void cpwait() {
    asm volatile("cp.async.wait_group %0;" :: "n"(N));
}
__device__ __forceinline__ void qbar(int wg) {
    asm volatile("bar.sync %0, 128;" :: "r"(wg + 1) : "memory");
}
// streaming store (.cs = cache-streaming, evict-first behavior; legal at v2.f32)
__device__ __forceinline__ void stg2_cs(float* p, float v0, float v1) {
    asm volatile("st.global.cs.v2.f32 [%0], {%1, %2};"
                 :: "l"(p), "f"(v0), "f"(v1) : "memory");
}
__device__ __forceinline__ float sigmoidf_(float z) {
    return 1.0f / (1.0f + __expf(-z));
}

// ---------------- prep: tf32-round W/U, zero h/c ----------------
__global__ void te_conv_kernel(const float* Wf, const float* Wb,
                               const float* Uf, const float* Ub) {
    int idx = blockIdx.x * 256 + threadIdx.x;          // 4 * 2^20 elements
    int which = idx >> 20, off = idx & 1048575;
    const float* src = (which == 0) ? Wf : (which == 1) ? Wb : (which == 2) ? Uf : Ub;
    float* dst = (which == 0) ? &g_Wt[0][0][0] : (which == 1) ? &g_Wt[1][0][0]
               : (which == 2) ? &g_Ut[0][0][0] : &g_Ut[1][0][0];
    dst[off] = __uint_as_float(f2tf(src[off]));
}

__global__ void te_zero_kernel() {
    int idx = blockIdx.x * 256 + threadIdx.x;          // 524288
    if (idx < 262144) (&g_h[0][0][0][0])[idx] = 0.0f;  // parity-0 h buffer
    else              (&g_c[0][0][0])[idx - 262144] = 0.0f;
}

// ---------------- projection: xW[dir][t] = emb[ids] @ W_dir + b_dir ----------------
#define P_AS 20
#define P_BS 136
__global__ __launch_bounds__(256) void te_proj_kernel(
        const int* __restrict__ x, const float* __restrict__ emb,
        const float* __restrict__ b_f, const float* __restrict__ b_b) {
    __shared__ __align__(16) float As[2][128 * P_AS];
    __shared__ __align__(16) float Bs[2][16 * P_BS];
    __shared__ int sid[128];

    int cta = blockIdx.x;                      // 8192
    int ct  = cta & 15;
    int mt  = (cta >> 4) & 1;
    int t   = (cta >> 5) & 127;
    int dir = cta >> 12;
    int n0 = mt * 128, c0 = ct * 128;
    int t_eff = dir ? (TT - 1 - t) : t;
    int tid = threadIdx.x;

    if (tid < 128) sid[tid] = x[(n0 + tid) * TT + t_eff];
    __syncthreads();

    const float* Wt = &g_Wt[dir][0][0];

    auto issue = [&](int kc, int bb) {
        int k0 = kc * 16;
        #pragma unroll
        for (int i = 0; i < 2; i++) {
            int o = tid + i * 256;
            int r = o >> 2, q = o & 3;
            cpa16(&As[bb][r * P_AS + q * 4],
                  emb + (size_t)sid[r] * EMBED + k0 + q * 4);
        }
        #pragma unroll
        for (int i = 0; i < 2; i++) {
            int o = tid + i * 256;
            int kk = o >> 5, q = o & 31;
            cpa16(&Bs[bb][kk * P_BS + q * 4],
                  Wt + (size_t)(k0 + kk) * G4 + c0 + q * 4);
        }
        cpcommit();
    };

    int lane = tid & 31, gid = lane >> 2, tig = lane & 3;
    int wid = tid >> 5, wy = wid >> 1, wx = wid & 1;
    int mbase = wy * 32, nbase = wx * 64;
    float acc[2][8][4];
    #pragma unroll
    for (int mi = 0; mi < 2; mi++)
        #pragma unroll
        for (int ni = 0; ni < 8; ni++)
            #pragma unroll
            for (int q = 0; q < 4; q++) acc[mi][ni][q] = 0.0f;

    auto compute = [&](int bb) {
        #pragma unroll
        for (int ks = 0; ks < 2; ks++) {
            int k = ks * 8;
            uint32_t a[2][4], b[8][2];
            #pragma unroll
            for (int mi = 0; mi < 2; mi++) {
                int m = mbase + mi * 16;
                a[mi][0] = f2tf(As[bb][(m + gid) * P_AS + k + tig]);
                a[mi][1] = f2tf(As[bb][(m + 8 + gid) * P_AS + k + tig]);
                a[mi][2] = f2tf(As[bb][(m + gid) * P_AS + k + tig + 4]);
                a[mi][3] = f2tf(As[bb][(m + 8 + gid) * P_AS + k + tig + 4]);
            }
            #pragma unroll
            for (int ni = 0; ni < 8; ni++) {
                int c = nbase + ni * 8 + gid;
                b[ni][0] = __float_as_uint(Bs[bb][(k + tig) * P_BS + c]);
                b[ni][1] = __float_as_uint(Bs[bb][(k + tig + 4) * P_BS + c]);
            }
            #pragma unroll
            for (int mi = 0; mi < 2; mi++)
                #pragma unroll
                for (int ni = 0; ni < 8; ni++)
                    mma8(acc[mi][ni], a[mi], b[ni]);
        }
    };

    const int NK = EMBED / 16;   // 32
    issue(0, 0);
    for (int kc = 0; kc < NK; kc++) {
        int bb = kc & 1;
        if (kc + 1 < NK) { issue(kc + 1, bb ^ 1); cpwait<1>(); }
        else             { cpwait<0>(); }
        __syncthreads();
        compute(bb);
        __syncthreads();
    }

    // epilogue: add bias, STREAMING store to g_xW (.cs: don't pollute L2)
    const float* bias = dir ? b_b : b_f;
    float* outp = &g_xW[dir][t][n0][0];
    #pragma unroll
    for (int mi = 0; mi < 2; mi++) {
        int r0 = mbase + mi * 16 + gid;
        #pragma unroll
        for (int ni = 0; ni < 8; ni++) {
            int c = c0 + nbase + ni * 8 + tig * 2;
            float b0v = bias[c], b1v = bias[c + 1];
            stg2_cs(outp + (size_t)r0 * G4 + c,
                    acc[mi][ni][0] + b0v, acc[mi][ni][1] + b1v);
            stg2_cs(outp + (size_t)(r0 + 8) * G4 + c,
                    acc[mi][ni][2] + b0v, acc[mi][ni][3] + b1v);
        }
    }
}

// ---------------- recurrent step (64x128 tile, 512 threads = 4 K-quads) ----------------
// Structure identical to R11 best; NEW: U loads pinned in L2 (evict_last policy),
// xW stream read with evict_first policy so it cannot evict U.
#define SA4   20      // A chunk row stride (16 + 4)
#define SB4   136     // B chunk row stride (128 + 8)
#define STG4  3456    // floats per stage: 64*SA4 + 16*SB4
#define SQ4   (3 * STG4)        // per-quad pipeline region (10368 floats)
#define ZST   136     // Z / xWs row stride
#define STEP_SMEM_FLOATS (4 * SQ4 + 64 * ZST + 2048 + 2048 + 64)   // 54336
#define STEP_SMEM_BYTES  (STEP_SMEM_FLOATS * 4)                     // 217344

__global__ __launch_bounds__(512) void te_step_kernel(const int* __restrict__ x, int t) {
    extern __shared__ __align__(16) float sm[];
    int tid  = threadIdx.x;
    int wg   = tid >> 7;          // quad id 0..3
    int qtid = tid & 127;

    int cta = blockIdx.x;         // 128
    int ut  = cta & 15;           // 32-unit tile
    int mt2 = (cta >> 4) & 3;     // 64-row tile
    int dir = cta >> 6;
    int u0 = ut * 32, n0 = mt2 * 64;
    int par = t & 1;
    int t_eff = dir ? (TT - 1 - t) : t;

    uint64_t pol_last  = mkpol_evict_last();    // for U (keep resident)
    uint64_t pol_first = mkpol_evict_first();   // for xW (streaming, no reuse)

    float* quadbase = sm + wg * SQ4;           // 3 stages: [A 64*SA4 | B 16*SB4]
    float* xWs = sm + 4 * SQ4;                 // 64*ZST
    float* cs  = xWs + 64 * ZST;               // 2048 (64 rows x 32 units)
    float* hs  = cs + 2048;                    // 2048
    int*  ids_s = (int*)(hs + 2048);           // 64

    const float* hbuf = &g_h[par][dir][0][0];
    const float* Ut   = &g_Ut[dir][0][0];
    const float* xWp  = &g_xW[dir][t][0][0];

    // ---- prefetch (group P): xW tile (evict_first), c, h_old, ids ----
    #pragma unroll
    for (int i = 0; i < 4; i++) {
        int o = tid + i * 512;                 // 2048 vec4 = 64 rows * 32 vec4
        int r = o >> 5, q = o & 31;            // tile col: gate=(q>>3), lu=(q&7)*4
        cpa16p(&xWs[r * ZST + q * 4],
               xWp + (size_t)(n0 + r) * G4 + (q >> 3) * 512 + u0 + (q & 7) * 4,
               pol_first);
    }
    {
        int r = tid >> 3, v = tid & 7;         // 512 vec4 = 64 rows * 8 vec4
        cpa16(&cs[r * 32 + v * 4], &g_c[dir][n0 + r][u0 + v * 4]);
        cpa16(&hs[r * 32 + v * 4], &g_h[par][dir][n0 + r][u0 + v * 4]);
    }
    if (tid < 64) cpa4(&ids_s[tid], &x[(n0 + tid) * TT + t_eff]);
    cpcommit();

    // ---- per-quad K-quarter pipeline (8 chunks of K=16, 3 stages) ----
    int kq0 = wg * 128;
    auto issue = [&](int kc, int s) {
        int k0 = kq0 + kc * 16;
        float* A = quadbase + s * STG4;
        float* B = quadbase + s * STG4 + 64 * SA4;
        #pragma unroll
        for (int i = 0; i < 2; i++) {          // A: 64 rows x 16 fl = 256 vec4
            int o = qtid + i * 128;
            int r = o >> 2, v = o & 3;
            cpa16(&A[r * SA4 + v * 4], hbuf + (size_t)(n0 + r) * UNITS + k0 + v * 4);
        }
        #pragma unroll
        for (int i = 0; i < 4; i++) {          // B: 16 k x 128 cols (U: evict_last)
            int o = qtid + i * 128;
            int kk = o >> 5, q = o & 31;
            int col = (q >> 3) * 512 + u0 + (q & 7) * 4;
            cpa16p(&B[kk * SB4 + q * 4], Ut + (size_t)(k0 + kk) * G4 + col, pol_last);
        }
        cpcommit();
    };

    int lane = tid & 31, gid = lane >> 2, tig = lane & 3;
    int wq = (tid >> 5) & 3, wy = wq >> 1, wx = wq & 1;
    int mbase = wy * 32, nbase = wx * 64;
    float acc[2][8][4];
    #pragma unroll
    for (int mi = 0; mi < 2; mi++)
        #pragma unroll
        for (int ni = 0; ni < 8; ni++)
            #pragma unroll
            for (int q = 0; q < 4; q++) acc[mi][ni][q] = 0.0f;

    auto compute = [&](int s) {
        float* Ab = quadbase + s * STG4;
        float* Bb = quadbase + s * STG4 + 64 * SA4;
        #pragma unroll
        for (int ks = 0; ks < 2; ks++) {
            int k = ks * 8;
            uint32_t a[2][4], b[8][2];
            #pragma unroll
            for (int mi = 0; mi < 2; mi++) {
                int m = mbase + mi * 16;
                a[mi][0] = f2tf(Ab[(m + gid) * SA4 + k + tig]);
                a[mi][1] = f2tf(Ab[(m + 8 + gid) * SA4 + k + tig]);
                a[mi][2] = f2tf(Ab[(m + gid) * SA4 + k + tig + 4]);
                a[mi][3] = f2tf(Ab[(m + 8 + gid) * SA4 + k + tig + 4]);
            }
            #pragma unroll
            for (int ni = 0; ni < 8; ni++) {
                int c = nbase + ni * 8 + gid;
                b[ni][0] = __float_as_uint(Bb[(k + tig) * SB4 + c]);
                b[ni][1] = __float_as_uint(Bb[(k + tig + 4) * SB4 + c]);
            }
            #pragma unroll
            for (int mi = 0; mi < 2; mi++)
                #pragma unroll
                for (int ni = 0; ni < 8; ni++)
                    mma8(acc[mi][ni], a[mi], b[ni]);
        }
    };

    // pipeline: preload 2, then 1 quad barrier per chunk.
    // WAR: issue(i+2) writes stage (i+2)%3 == (i-1)%3, last read at compute(i-1);
    // the qbar at iter i orders all quad warps past compute(i-1).
    issue(0, 0);
    issue(1, 1);
    for (int kc = 0; kc < 8; kc++) {
        int s = kc % 3;
        cpwait<1>();
        qbar(wg);
        if (kc + 2 < 8) issue(kc + 2, (kc + 2) % 3);
        compute(s);
    }
    cpwait<0>();
    qbar(wg);   // all quad warps past compute(7) before Z overwrites pipeline SMEM

    // ---- partials to SMEM (Z[wg] aliases this quad's dead pipeline region) ----
    float* Zq = quadbase;                      // 64*ZST = 8704 fl <= SQ4
    #pragma unroll
    for (int mi = 0; mi < 2; mi++) {
        int r0 = mbase + mi * 16 + gid;
        #pragma unroll
        for (int ni = 0; ni < 8; ni++) {
            int c = nbase + ni * 8 + tig * 2;
            Zq[r0 * ZST + c]           = acc[mi][ni][0];
            Zq[r0 * ZST + c + 1]       = acc[mi][ni][1];
            Zq[(r0 + 8) * ZST + c]     = acc[mi][ni][2];
            Zq[(r0 + 8) * ZST + c + 1] = acc[mi][ni][3];
        }
    }
    __syncthreads();

    // ---- LSTM gate update (sum 4 partials + xW); cols: gate*32 + lu ----
    float* Z0 = sm;
    float* Z1 = sm + SQ4;
    float* Z2 = sm + 2 * SQ4;
    float* Z3 = sm + 3 * SQ4;
    #pragma unroll
    for (int i = 0; i < 4; i++) {
        int item = tid + i * 512;              // 2048 = 64 rows * 32 units
        int r = item >> 5, lu = item & 31;
        int n = n0 + r, u = u0 + lu;
        float zi = Z0[r * ZST + lu]      + Z1[r * ZST + lu]
                 + Z2[r * ZST + lu]      + Z3[r * ZST + lu]      + xWs[r * ZST + lu];
        float zf = Z0[r * ZST + 32 + lu] + Z1[r * ZST + 32 + lu]
                 + Z2[r * ZST + 32 + lu] + Z3[r * ZST + 32 + lu] + xWs[r * ZST + 32 + lu];
        float zg = Z0[r * ZST + 64 + lu] + Z1[r * ZST + 64 + lu]
                 + Z2[r * ZST + 64 + lu] + Z3[r * ZST + 64 + lu] + xWs[r * ZST + 64 + lu];
        float zo = Z0[r * ZST + 96 + lu] + Z1[r * ZST + 96 + lu]
                 + Z2[r * ZST + 96 + lu] + Z3[r * ZST + 96 + lu] + xWs[r * ZST + 96 + lu];
        float ig = sigmoidf_(zi);
        float fg = sigmoidf_(zf);
        float gg = tanhf(zg);
        float og = sigmoidf_(zo);
        float co = cs[r * 32 + lu];
        float cn = fg * co + ig * gg;
        float hn = og * tanhf(cn);
        bool msk = (ids_s[r] != 0);
        float ho = hs[r * 32 + lu];
        g_h[par ^ 1][dir][n][u] = msk ? hn : ho;
        g_c[dir][n][u]          = msk ? cn : co;
    }
}

// ---------------- final: out[n] = concat(h_fwd, h_bwd) ----------------
__global__ void te_final_kernel(float* __restrict__ out) {
    int idx = blockIdx.x * 256 + threadIdx.x;   // 256*1024
    int n = idx >> 10, j = idx & 1023;
    out[idx] = (j < 512) ? g_h[0][0][n][j] : g_h[0][1][n][j - 512];
}

// ---------------- launch ----------------
extern "C" void kernel_launch(void* const* d_in, const int* in_sizes, int n_in,
                              void* d_out, int out_size) {
    const int*   x    = (const int*)d_in[0];
    const float* emb  = (const float*)d_in[1];
    const float* W_f  = (const float*)d_in[2];
    const float* U_f  = (const float*)d_in[3];
    const float* b_f  = (const float*)d_in[4];
    const float* W_b  = (const float*)d_in[5];
    const float* U_b  = (const float*)d_in[6];
    const float* b_b  = (const float*)d_in[7];
    float* out = (float*)d_out;

    cudaFuncSetAttribute(te_step_kernel,
                         cudaFuncAttributeMaxDynamicSharedMemorySize, STEP_SMEM_BYTES);

    te_conv_kernel<<<16384, 256>>>(W_f, W_b, U_f, U_b);
    te_zero_kernel<<<2048, 256>>>();
    te_proj_kernel<<<8192, 256>>>(x, emb, b_f, b_b);
    for (int t = 0; t < TT; t++)
        te_step_kernel<<<128, 512, STEP_SMEM_BYTES>>>(x, t);
    te_final_kernel<<<1024, 256>>>(out);
}